// round 15
// baseline (speedup 1.0000x reference)
#include <cuda_runtime.h>
#include <cuda_bf16.h>

#define NN 100000
#define NE 3200000

// PDL primitives
#define GDC_WAIT()   asm volatile("griddepcontrol.wait;" ::: "memory")
#define GDC_LAUNCH() asm volatile("griddepcontrol.launch_dependents;" ::: "memory")

// ---------------- scratch (device globals: allocation-free) ----------------
__device__ int2   g_edges[NE];   // packed edges (int64 input path only)
__device__ int    g_deg[NN];     // zeroed by memsetAsync; true degree = g_deg+1
__device__ float4 g_t4[NN];      // scaled node features (gather source)
__device__ float4 g_aggA[NN];    // layer-1 accumulator
__device__ float4 g_aggB[NN];    // layer-2 accumulator
__device__ float2 g_t2[NN];      // layer-3 scaled features
__device__ float2 g_agg2[NN];    // layer-3 accumulator
__device__ int    g_idx32;       // 1 if edge_index is int32 (written by k_hist)

// ---------------- histogram: detect + degree count (+ pack for int64) ----------
// Signals launch_dependents at ENTRY so k_gemv1's x-stream runs concurrently.
#define HBLK 1184
__global__ void __launch_bounds__(256) k_hist(const void* __restrict__ eiv) {
    GDC_LAUNCH();                                    // let k_gemv1 start streaming
    __shared__ int s_i32;
    if (threadIdx.x < 32) {
        long long val = ((const long long*)eiv)[threadIdx.x];
        unsigned bad = __ballot_sync(0xffffffffu, val < 0 || val >= NN);
        if (threadIdx.x == 0) {
            s_i32 = bad ? 1 : 0;
            if (blockIdx.x == 0) g_idx32 = s_i32;    // for downstream kernels
        }
    }
    __syncthreads();
    const int i32 = s_i32;
    const int gt = blockIdx.x * 256 + threadIdx.x;
    const int T  = HBLK * 256;
    if (i32) {
        const int* ei32 = (const int*)eiv;
        for (int b = gt * 4; b < NE; b += T * 4) {
            int4 cc = __ldg((const int4*)(ei32 + NE + b));
            atomicAdd(&g_deg[cc.x], 1);
            atomicAdd(&g_deg[cc.y], 1);
            atomicAdd(&g_deg[cc.z], 1);
            atomicAdd(&g_deg[cc.w], 1);
        }
    } else {
        const long long* ei = (const long long*)eiv;
        for (int e = gt; e < NE; e += T) {
            int r = (int)ei[e];
            int c = (int)ei[NE + e];
            g_edges[e] = make_int2(r, c);
            atomicAdd(&g_deg[c], 1);
        }
    }
}

// ---------------- GEMV: acc = x@W1 (pre-wait), then scale + self-loop ----------
// One warp per node, one pass (no grid-stride). All heavy streaming happens
// BEFORE GDC_WAIT — it only touches harness inputs, so it overlaps k_hist.
__global__ void __launch_bounds__(256) k_gemv1(const float* __restrict__ x,
                                               const float* __restrict__ W1) {
    __shared__ float sW[512];
    for (int i = threadIdx.x; i < 512; i += 256) sW[i] = __ldg(W1 + i);
    __syncthreads();
    const int gw   = (blockIdx.x * 256 + threadIdx.x) >> 5;   // node
    const int lane = threadIdx.x & 31;
    float acc[4] = {0.f, 0.f, 0.f, 0.f};
    if (gw < NN) {
        float4 xr = __ldg((const float4*)x + (size_t)gw * 32 + lane);
        float xs[4] = {xr.x, xr.y, xr.z, xr.w};
        #pragma unroll
        for (int i = 0; i < 4; i++) {
            int k = lane * 4 + i;
            #pragma unroll
            for (int j = 0; j < 4; j++) acc[j] += xs[i] * sW[k * 4 + j];
        }
        #pragma unroll
        for (int o = 16; o > 0; o >>= 1) {
            #pragma unroll
            for (int j = 0; j < 4; j++)
                acc[j] += __shfl_xor_sync(0xffffffffu, acc[j], o);
        }
    }
    GDC_WAIT();                                   // histogram done: deg valid
    if (gw < NN && lane == 0) {
        float d  = rsqrtf((float)(g_deg[gw] + 1));
        float4 t = make_float4(acc[0] * d, acc[1] * d, acc[2] * d, acc[3] * d);
        g_t4[gw]   = t;
        g_aggA[gw] = t;                           // self-loop contribution
    }
}

// ---------------- edge scatter: agg[row] += t4[col]  (2 edges/thread) ----------
template <int PHASE>   // 0: aggA, 1: aggB
__global__ void __launch_bounds__(256) k_scatter4(const int* __restrict__ ei32) {
    int base = (blockIdx.x * 256 + threadIdx.x) * 2;
    GDC_WAIT();
    if (base >= NE) return;
    float4* agg = (PHASE == 0) ? g_aggA : g_aggB;
    int r0, c0, r1, c1;
    if (g_idx32) {
        int2 rr = __ldg((const int2*)(ei32 + base));
        int2 cc = __ldg((const int2*)(ei32 + NE + base));
        r0 = rr.x; r1 = rr.y; c0 = cc.x; c1 = cc.y;
    } else {
        int4 p = *(const int4*)(g_edges + base);
        r0 = p.x; c0 = p.y; r1 = p.z; c1 = p.w;
    }
    float4 v0 = __ldg(g_t4 + c0);
    float4 v1 = __ldg(g_t4 + c1);
    asm volatile("red.global.add.v4.f32 [%0], {%1,%2,%3,%4};"
                 :: "l"(agg + r0), "f"(v0.x), "f"(v0.y), "f"(v0.z), "f"(v0.w) : "memory");
    asm volatile("red.global.add.v4.f32 [%0], {%1,%2,%3,%4};"
                 :: "l"(agg + r1), "f"(v1.x), "f"(v1.y), "f"(v1.z), "f"(v1.w) : "memory");
}

__global__ void __launch_bounds__(256) k_scatter2(const int* __restrict__ ei32) {
    int base = (blockIdx.x * 256 + threadIdx.x) * 2;
    GDC_WAIT();
    if (base >= NE) return;
    int r0, c0, r1, c1;
    if (g_idx32) {
        int2 rr = __ldg((const int2*)(ei32 + base));
        int2 cc = __ldg((const int2*)(ei32 + NE + base));
        r0 = rr.x; r1 = rr.y; c0 = cc.x; c1 = cc.y;
    } else {
        int4 p = *(const int4*)(g_edges + base);
        r0 = p.x; c0 = p.y; r1 = p.z; c1 = p.w;
    }
    float2 v0 = __ldg(g_t2 + c0);
    float2 v1 = __ldg(g_t2 + c1);
    asm volatile("red.global.add.v2.f32 [%0], {%1,%2};"
                 :: "l"(g_agg2 + r0), "f"(v0.x), "f"(v0.y) : "memory");
    asm volatile("red.global.add.v2.f32 [%0], {%1,%2};"
                 :: "l"(g_agg2 + r1), "f"(v1.x), "f"(v1.y) : "memory");
}

// ---------------- layer 2 transform ----------------
__global__ void __launch_bounds__(256) k_l2(const float* __restrict__ W2,
                                            const float* __restrict__ b1) {
    int v = blockIdx.x * blockDim.x + threadIdx.x;
    GDC_WAIT();
    if (v >= NN) return;
    float d  = rsqrtf((float)(g_deg[v] + 1));
    float4 a = g_aggA[v];
    float h0 = tanhf(fmaf(a.x, d, __ldg(b1 + 0)));
    float h1 = tanhf(fmaf(a.y, d, __ldg(b1 + 1)));
    float h2 = tanhf(fmaf(a.z, d, __ldg(b1 + 2)));
    float h3 = tanhf(fmaf(a.w, d, __ldg(b1 + 3)));
    float t[4];
    #pragma unroll
    for (int j = 0; j < 4; j++)
        t[j] = (h0 * __ldg(W2 + j)     + h1 * __ldg(W2 + 4 + j)
              + h2 * __ldg(W2 + 8 + j) + h3 * __ldg(W2 + 12 + j)) * d;
    float4 tv = make_float4(t[0], t[1], t[2], t[3]);
    g_t4[v]   = tv;
    g_aggB[v] = tv;
}

// ---------------- layer 3 transform ----------------
__global__ void __launch_bounds__(256) k_l3(const float* __restrict__ W3,
                                            const float* __restrict__ b2) {
    int v = blockIdx.x * blockDim.x + threadIdx.x;
    GDC_WAIT();
    if (v >= NN) return;
    float d  = rsqrtf((float)(g_deg[v] + 1));
    float4 a = g_aggB[v];
    float h0 = tanhf(fmaf(a.x, d, __ldg(b2 + 0)));
    float h1 = tanhf(fmaf(a.y, d, __ldg(b2 + 1)));
    float h2 = tanhf(fmaf(a.z, d, __ldg(b2 + 2)));
    float h3 = tanhf(fmaf(a.w, d, __ldg(b2 + 3)));
    float t0 = (h0 * __ldg(W3 + 0) + h1 * __ldg(W3 + 2)
              + h2 * __ldg(W3 + 4) + h3 * __ldg(W3 + 6)) * d;
    float t1 = (h0 * __ldg(W3 + 1) + h1 * __ldg(W3 + 3)
              + h2 * __ldg(W3 + 5) + h3 * __ldg(W3 + 7)) * d;
    float2 tv = make_float2(t0, t1);
    g_t2[v]   = tv;
    g_agg2[v] = tv;
}

// ---------------- epilogue ----------------
__global__ void __launch_bounds__(256) k_final(const float* __restrict__ b3,
                                               const float* __restrict__ Wc,
                                               const float* __restrict__ bc,
                                               float* __restrict__ out,
                                               int write_h) {
    int v = blockIdx.x * blockDim.x + threadIdx.x;
    GDC_WAIT();
    if (v >= NN) return;
    float d  = rsqrtf((float)(g_deg[v] + 1));
    float2 a = g_agg2[v];
    float h0 = tanhf(fmaf(a.x, d, __ldg(b3 + 0)));
    float h1 = tanhf(fmaf(a.y, d, __ldg(b3 + 1)));
    float4 o;
    o.x = h0 * __ldg(Wc + 0) + h1 * __ldg(Wc + 4) + __ldg(bc + 0);
    o.y = h0 * __ldg(Wc + 1) + h1 * __ldg(Wc + 5) + __ldg(bc + 1);
    o.z = h0 * __ldg(Wc + 2) + h1 * __ldg(Wc + 6) + __ldg(bc + 2);
    o.w = h0 * __ldg(Wc + 3) + h1 * __ldg(Wc + 7) + __ldg(bc + 3);
    ((float4*)out)[v] = o;                                  // out [N,4]
    if (write_h)
        ((float2*)(out + 4 * NN))[v] = make_float2(h0, h1); // h [N,2]
}

// ---------------- host ----------------
template <typename... Args>
static void launch_pdl(void (*kern)(Args...), int grid, int block, Args... args) {
    cudaLaunchConfig_t cfg = {};
    cfg.gridDim  = dim3(grid, 1, 1);
    cfg.blockDim = dim3(block, 1, 1);
    cudaLaunchAttribute attr[1];
    attr[0].id = cudaLaunchAttributeProgrammaticStreamSerialization;
    attr[0].val.programmaticStreamSerializationAllowed = 1;
    cfg.attrs = attr;
    cfg.numAttrs = 1;
    cudaLaunchKernelEx(&cfg, kern, args...);
}

extern "C" void kernel_launch(void* const* d_in, const int* in_sizes, int n_in,
                              void* d_out, int out_size) {
    const float* x  = (const float*)d_in[0];
    const void*  ei = d_in[1];
    const float* W1 = (const float*)d_in[2];
    const float* b1 = (const float*)d_in[3];
    const float* W2 = (const float*)d_in[4];
    const float* b2 = (const float*)d_in[5];
    const float* W3 = (const float*)d_in[6];
    const float* b3 = (const float*)d_in[7];
    const float* Wc = (const float*)d_in[8];
    const float* bc = (const float*)d_in[9];
    float* out = (float*)d_out;

    const int nbN  = (NN + 255) / 256;
    const int nbW  = (NN + 7) / 8;              // warp-per-node, single pass
    const int nbE2 = NE / (256 * 2);            // 2 edges/thread (exact: 6250)
    const int write_h = (out_size >= 6 * NN) ? 1 : 0;

    void* degp = nullptr;
    cudaGetSymbolAddress(&degp, g_deg);
    cudaMemsetAsync(degp, 0, NN * sizeof(int)); // deg counter; true degree = deg+1

    k_hist<<<HBLK, 256>>>(ei);                  // signals launch_dependents at entry

    launch_pdl(k_gemv1, nbW, 256, x, W1);       // streams x pre-wait, scales post-wait
    launch_pdl(k_scatter4<0>, nbE2, 256, (const int*)ei);
    launch_pdl(k_l2, nbN, 256, W2, b1);
    launch_pdl(k_scatter4<1>, nbE2, 256, (const int*)ei);
    launch_pdl(k_l3, nbN, 256, W3, b2);
    launch_pdl(k_scatter2, nbE2, 256, (const int*)ei);
    launch_pdl(k_final, nbN, 256, b3, Wc, bc, out, write_h);
}

// round 17
// speedup vs baseline: 1.0679x; 1.0679x over previous
#include <cuda_runtime.h>
#include <cuda_bf16.h>

#define NN 100000
#define NE 3200000

// PDL primitives
#define GDC_WAIT()   asm volatile("griddepcontrol.wait;" ::: "memory")
#define GDC_LAUNCH() asm volatile("griddepcontrol.launch_dependents;" ::: "memory")

// ---------------- scratch (device globals: allocation-free) ----------------
__device__ int2   g_edges[NE];   // packed edges (int64 input path only)
__device__ int    g_deg[NN];     // zeroed by memsetAsync; true degree = g_deg+1
__device__ float4 g_t4[NN];      // scaled node features (gather source)
__device__ float4 g_aggA[NN];    // layer-1 accumulator
__device__ float4 g_aggB[NN];    // layer-2 accumulator
__device__ float2 g_t2[NN];      // layer-3 scaled features
__device__ float2 g_agg2[NN];    // layer-3 accumulator
__device__ int    g_idx32;       // 1 if edge_index is int32 (written by k_fused)

// ---------------- fused: GEMV (x@W1, unscaled) || degree histogram ----------------
// Proven R12/R13 structure: block-split, disjoint resources, no ordering needed.
#define GB 444
#define HB 444
__global__ void __launch_bounds__(256) k_fused(const void* __restrict__ eiv,
                                               const float* __restrict__ x,
                                               const float* __restrict__ W1) {
    if (blockIdx.x < GB) {
        __shared__ float sW[512];
        for (int i = threadIdx.x; i < 512; i += 256) sW[i] = W1[i];
        __syncthreads();
        const int lane = threadIdx.x & 31;
        const int warps = GB * 8;
        for (int v = (blockIdx.x * 256 + threadIdx.x) >> 5; v < NN; v += warps) {
            float4 xr = __ldg((const float4*)x + (size_t)v * 32 + lane);
            float xs[4] = {xr.x, xr.y, xr.z, xr.w};
            float acc[4] = {0.f, 0.f, 0.f, 0.f};
            #pragma unroll
            for (int i = 0; i < 4; i++) {
                int k = lane * 4 + i;
                #pragma unroll
                for (int j = 0; j < 4; j++) acc[j] += xs[i] * sW[k * 4 + j];
            }
            #pragma unroll
            for (int o = 16; o > 0; o >>= 1) {
                #pragma unroll
                for (int j = 0; j < 4; j++)
                    acc[j] += __shfl_xor_sync(0xffffffffu, acc[j], o);
            }
            if (lane == 0)
                g_t4[v] = make_float4(acc[0], acc[1], acc[2], acc[3]);  // unscaled
        }
    } else {
        __shared__ int s_i32;
        if (threadIdx.x < 32) {
            long long val = ((const long long*)eiv)[threadIdx.x];
            unsigned bad = __ballot_sync(0xffffffffu, val < 0 || val >= NN);
            if (threadIdx.x == 0) {
                s_i32 = bad ? 1 : 0;
                if (blockIdx.x == GB) g_idx32 = s_i32;   // publish for later kernels
            }
        }
        __syncthreads();
        const int i32 = s_i32;
        const int gt = (blockIdx.x - GB) * 256 + threadIdx.x;
        const int T  = HB * 256;
        if (i32) {
            const int* ei32 = (const int*)eiv;
            for (int b = gt * 4; b < NE; b += T * 4) {
                int4 cc = __ldg((const int4*)(ei32 + NE + b));
                atomicAdd(&g_deg[cc.x], 1);
                atomicAdd(&g_deg[cc.y], 1);
                atomicAdd(&g_deg[cc.z], 1);
                atomicAdd(&g_deg[cc.w], 1);
            }
        } else {
            const long long* ei = (const long long*)eiv;
            for (int e = gt; e < NE; e += T) {
                int r = (int)ei[e];
                int c = (int)ei[NE + e];
                g_edges[e] = make_int2(r, c);
                atomicAdd(&g_deg[c], 1);
            }
        }
    }
}

// ---------------- scale: t4 *= dinv ; aggA = t4 (self-loop) ----------------
__global__ void __launch_bounds__(256) k_scale() {
    int v = blockIdx.x * blockDim.x + threadIdx.x;
    GDC_WAIT();
    GDC_LAUNCH();                        // scatter<0> dispatches + pre-loads indices
    if (v >= NN) return;
    float d  = rsqrtf((float)(g_deg[v] + 1));
    float4 a = g_t4[v];
    float4 t = make_float4(a.x * d, a.y * d, a.z * d, a.w * d);
    g_t4[v]   = t;
    g_aggA[v] = t;
}

// ---------------- edge scatter: agg[row] += t4[col]  (2 edges/thread) ----------
// Index data (g_idx32, g_edges, ei32) is final since k_fused, which transitively
// completed before this kernel could launch — safe to load PRE-wait.
template <int PHASE>   // 0: aggA, 1: aggB
__global__ void __launch_bounds__(256) k_scatter4(const int* __restrict__ ei32) {
    int base = (blockIdx.x * 256 + threadIdx.x) * 2;
    int r0 = 0, c0 = 0, r1 = 0, c1 = 0;
    const bool act = (base < NE);
    if (act) {
        if (g_idx32) {
            int2 rr = __ldg((const int2*)(ei32 + base));
            int2 cc = __ldg((const int2*)(ei32 + NE + base));
            r0 = rr.x; r1 = rr.y; c0 = cc.x; c1 = cc.y;
        } else {
            int4 p = *(const int4*)(g_edges + base);
            r0 = p.x; c0 = p.y; r1 = p.z; c1 = p.w;
        }
    }
    GDC_WAIT();                          // t4 / agg now valid
    GDC_LAUNCH();                        // next transform dispatches early
    if (!act) return;
    float4* agg = (PHASE == 0) ? g_aggA : g_aggB;
    float4 v0 = __ldg(g_t4 + c0);
    float4 v1 = __ldg(g_t4 + c1);
    asm volatile("red.global.add.v4.f32 [%0], {%1,%2,%3,%4};"
                 :: "l"(agg + r0), "f"(v0.x), "f"(v0.y), "f"(v0.z), "f"(v0.w) : "memory");
    asm volatile("red.global.add.v4.f32 [%0], {%1,%2,%3,%4};"
                 :: "l"(agg + r1), "f"(v1.x), "f"(v1.y), "f"(v1.z), "f"(v1.w) : "memory");
}

__global__ void __launch_bounds__(256) k_scatter2(const int* __restrict__ ei32) {
    int base = (blockIdx.x * 256 + threadIdx.x) * 2;
    int r0 = 0, c0 = 0, r1 = 0, c1 = 0;
    const bool act = (base < NE);
    if (act) {
        if (g_idx32) {
            int2 rr = __ldg((const int2*)(ei32 + base));
            int2 cc = __ldg((const int2*)(ei32 + NE + base));
            r0 = rr.x; r1 = rr.y; c0 = cc.x; c1 = cc.y;
        } else {
            int4 p = *(const int4*)(g_edges + base);
            r0 = p.x; c0 = p.y; r1 = p.z; c1 = p.w;
        }
    }
    GDC_WAIT();
    GDC_LAUNCH();
    if (!act) return;
    float2 v0 = __ldg(g_t2 + c0);
    float2 v1 = __ldg(g_t2 + c1);
    asm volatile("red.global.add.v2.f32 [%0], {%1,%2};"
                 :: "l"(g_agg2 + r0), "f"(v0.x), "f"(v0.y) : "memory");
    asm volatile("red.global.add.v2.f32 [%0], {%1,%2};"
                 :: "l"(g_agg2 + r1), "f"(v1.x), "f"(v1.y) : "memory");
}

// ---------------- layer 2 transform ----------------
// Pre-wait: deg (stable since k_fused) + weights/biases (harness inputs).
__global__ void __launch_bounds__(256) k_l2(const float* __restrict__ W2,
                                            const float* __restrict__ b1) {
    int v = blockIdx.x * blockDim.x + threadIdx.x;
    float d = 0.f, w[16], bb[4];
    if (v < NN) {
        d = rsqrtf((float)(g_deg[v] + 1));
        #pragma unroll
        for (int j = 0; j < 16; j++) w[j] = __ldg(W2 + j);
        #pragma unroll
        for (int j = 0; j < 4; j++) bb[j] = __ldg(b1 + j);
    }
    GDC_WAIT();
    GDC_LAUNCH();
    if (v >= NN) return;
    float4 a = g_aggA[v];
    float h0 = tanhf(fmaf(a.x, d, bb[0]));
    float h1 = tanhf(fmaf(a.y, d, bb[1]));
    float h2 = tanhf(fmaf(a.z, d, bb[2]));
    float h3 = tanhf(fmaf(a.w, d, bb[3]));
    float t[4];
    #pragma unroll
    for (int j = 0; j < 4; j++)
        t[j] = (h0 * w[j] + h1 * w[4 + j] + h2 * w[8 + j] + h3 * w[12 + j]) * d;
    float4 tv = make_float4(t[0], t[1], t[2], t[3]);
    g_t4[v]   = tv;
    g_aggB[v] = tv;
}

// ---------------- layer 3 transform ----------------
__global__ void __launch_bounds__(256) k_l3(const float* __restrict__ W3,
                                            const float* __restrict__ b2) {
    int v = blockIdx.x * blockDim.x + threadIdx.x;
    float d = 0.f, w[8], bb[4];
    if (v < NN) {
        d = rsqrtf((float)(g_deg[v] + 1));
        #pragma unroll
        for (int j = 0; j < 8; j++) w[j] = __ldg(W3 + j);
        #pragma unroll
        for (int j = 0; j < 4; j++) bb[j] = __ldg(b2 + j);
    }
    GDC_WAIT();
    GDC_LAUNCH();
    if (v >= NN) return;
    float4 a = g_aggB[v];
    float h0 = tanhf(fmaf(a.x, d, bb[0]));
    float h1 = tanhf(fmaf(a.y, d, bb[1]));
    float h2 = tanhf(fmaf(a.z, d, bb[2]));
    float h3 = tanhf(fmaf(a.w, d, bb[3]));
    float t0 = (h0 * w[0] + h1 * w[2] + h2 * w[4] + h3 * w[6]) * d;
    float t1 = (h0 * w[1] + h1 * w[3] + h2 * w[5] + h3 * w[7]) * d;
    float2 tv = make_float2(t0, t1);
    g_t2[v]   = tv;
    g_agg2[v] = tv;
}

// ---------------- epilogue ----------------
__global__ void __launch_bounds__(256) k_final(const float* __restrict__ b3,
                                               const float* __restrict__ Wc,
                                               const float* __restrict__ bc,
                                               float* __restrict__ out,
                                               int write_h) {
    int v = blockIdx.x * blockDim.x + threadIdx.x;
    float d = 0.f, w[8], b3r[2], bcr[4];
    if (v < NN) {
        d = rsqrtf((float)(g_deg[v] + 1));
        #pragma unroll
        for (int j = 0; j < 8; j++) w[j] = __ldg(Wc + j);
        b3r[0] = __ldg(b3 + 0); b3r[1] = __ldg(b3 + 1);
        #pragma unroll
        for (int j = 0; j < 4; j++) bcr[j] = __ldg(bc + j);
    }
    GDC_WAIT();
    if (v >= NN) return;
    float2 a = g_agg2[v];
    float h0 = tanhf(fmaf(a.x, d, b3r[0]));
    float h1 = tanhf(fmaf(a.y, d, b3r[1]));
    float4 o;
    o.x = h0 * w[0] + h1 * w[4] + bcr[0];
    o.y = h0 * w[1] + h1 * w[5] + bcr[1];
    o.z = h0 * w[2] + h1 * w[6] + bcr[2];
    o.w = h0 * w[3] + h1 * w[7] + bcr[3];
    ((float4*)out)[v] = o;                                  // out [N,4]
    if (write_h)
        ((float2*)(out + 4 * NN))[v] = make_float2(h0, h1); // h [N,2]
}

// ---------------- host ----------------
template <typename... Args>
static void launch_pdl(void (*kern)(Args...), int grid, int block, Args... args) {
    cudaLaunchConfig_t cfg = {};
    cfg.gridDim  = dim3(grid, 1, 1);
    cfg.blockDim = dim3(block, 1, 1);
    cudaLaunchAttribute attr[1];
    attr[0].id = cudaLaunchAttributeProgrammaticStreamSerialization;
    attr[0].val.programmaticStreamSerializationAllowed = 1;
    cfg.attrs = attr;
    cfg.numAttrs = 1;
    cudaLaunchKernelEx(&cfg, kern, args...);
}

extern "C" void kernel_launch(void* const* d_in, const int* in_sizes, int n_in,
                              void* d_out, int out_size) {
    const float* x  = (const float*)d_in[0];
    const void*  ei = d_in[1];
    const float* W1 = (const float*)d_in[2];
    const float* b1 = (const float*)d_in[3];
    const float* W2 = (const float*)d_in[4];
    const float* b2 = (const float*)d_in[5];
    const float* W3 = (const float*)d_in[6];
    const float* b3 = (const float*)d_in[7];
    const float* Wc = (const float*)d_in[8];
    const float* bc = (const float*)d_in[9];
    float* out = (float*)d_out;

    const int nbN  = (NN + 255) / 256;
    const int nbE2 = NE / (256 * 2);            // 2 edges/thread (exact: 6250)
    const int write_h = (out_size >= 6 * NN) ? 1 : 0;

    void* degp = nullptr;
    cudaGetSymbolAddress(&degp, g_deg);
    cudaMemsetAsync(degp, 0, NN * sizeof(int)); // deg counter; true degree = deg+1

    k_fused<<<GB + HB, 256>>>(ei, x, W1);       // GEMV || (detect + histogram)

    launch_pdl(k_scale, nbN, 256);
    launch_pdl(k_scatter4<0>, nbE2, 256, (const int*)ei);
    launch_pdl(k_l2, nbN, 256, W2, b1);
    launch_pdl(k_scatter4<1>, nbE2, 256, (const int*)ei);
    launch_pdl(k_l3, nbN, 256, W3, b2);
    launch_pdl(k_scatter2, nbE2, 256, (const int*)ei);
    launch_pdl(k_final, nbN, 256, b3, Wc, bc, out, write_h);
}